// round 5
// baseline (speedup 1.0000x reference)
#include <cuda_runtime.h>

// MatrixReconstructionLayer: X[B,8]=[f1,f2,rx,ry,rz,tx,ty,tz] -> F[B,9] (3x3 row-major).
// F = K2inv @ T @ R @ K1inv, closed-form. MUFU sin/cos + fast divide
// (rel_err ~1e-6 vs 1e-3 budget).
//
// R4 (resubmit after infra failure): input staged through smem. Global loads
// are fully coalesced float4 (4 lines/warp instead of 8), rows re-read from a
// 48B-stride padded layout (LDS.128 bank-conflict-free). One 24KB union
// buffer (input stage, then output stage) -> 8 blocks/SM, 100% occupancy.

#define EPSF 1e-8f
#define TPB 256
#define RPB (TPB * 2)           // 512 rows per block
#define IN_STRIDE 12            // floats per staged input row (8 used + 4 pad)

__device__ __forceinline__ void compute_row(const float4 a, const float4 b,
                                            float* __restrict__ sr) {
    const float f1 = a.x, f2 = a.y, rx = a.z, ry = a.w;
    const float rz = b.x, tx = b.y, ty = b.z, tz = b.w;

    const float sx = __sinf(rx), cx = __cosf(rx);
    const float sy = __sinf(ry), cy = __cosf(ry);
    const float sz = __sinf(rz), cz = __cosf(rz);

    const float k1 = -__fdividef(1.0f, f1 + EPSF);
    const float k2 = -__fdividef(1.0f, f2 + EPSF);

    // R = Rx @ (Ry @ Rz)
    const float sxsy = sx * sy;
    const float cxsy = cx * sy;

    const float r00 = cy * cz;
    const float r01 = -cy * sz;
    const float r02 = -sy;
    const float r10 = cx * sz - sxsy * cz;
    const float r11 = cx * cz + sxsy * sz;
    const float r12 = -sx * cy;
    const float r20 = sx * sz + cxsy * cz;
    const float r21 = sx * cz - cxsy * sz;
    const float r22 = cx * cy;

    // M = skew(t) @ R
    const float m00 = ty * r20 - tz * r10;
    const float m01 = ty * r21 - tz * r11;
    const float m02 = ty * r22 - tz * r12;
    const float m10 = tz * r00 - tx * r20;
    const float m11 = tz * r01 - tx * r21;
    const float m12 = tz * r02 - tx * r22;
    const float m20 = tx * r10 - ty * r00;
    const float m21 = tx * r11 - ty * r01;
    const float m22 = tx * r12 - ty * r02;

    // F = diag(k2,k2,1) @ M @ diag(k1,k1,1)
    const float k21 = k2 * k1;
    sr[0] = k21 * m00;
    sr[1] = k21 * m01;
    sr[2] = k2 * m02;
    sr[3] = k21 * m10;
    sr[4] = k21 * m11;
    sr[5] = k2 * m12;
    sr[6] = m20 * k1;
    sr[7] = m21 * k1;
    sr[8] = m22;
}

// Fast path: B % RPB == 0.
__global__ __launch_bounds__(TPB)
void fmat_kernel_fast(const float* __restrict__ X, float* __restrict__ out) {
    // Union buffer: input stage needs RPB*IN_STRIDE = 6144 floats (24KB);
    // output stage needs RPB*9 = 4608 floats. Reused across a barrier.
    __shared__ __align__(16) float s[RPB * IN_STRIDE];

    const int tid = threadIdx.x;
    const unsigned blk = blockIdx.x;
    const float4* Xv = reinterpret_cast<const float4*>(X);

    // 1) Fully coalesced input load: block = 1024 consecutive float4.
    float4 v[4];
#pragma unroll
    for (int k = 0; k < 4; k++)
        v[k] = __ldcs(&Xv[blk * (RPB * 2u) + (unsigned)(k * TPB + tid)]);

    // 2) Stage into padded row layout: global float4 j -> row j/2, half j&1,
    //    at float offset row*12 + half*4 (16B aligned).
#pragma unroll
    for (int k = 0; k < 4; k++) {
        const int j = k * TPB + tid;
        float4* dst = reinterpret_cast<float4*>(&s[(j >> 1) * IN_STRIDE + (j & 1) * 4]);
        *dst = v[k];
    }
    __syncthreads();

    // 3) Read own rows (tid, tid+TPB). 48B stride => conflict-free LDS.128.
    const float4 a0 = *reinterpret_cast<const float4*>(&s[tid * IN_STRIDE]);
    const float4 b0 = *reinterpret_cast<const float4*>(&s[tid * IN_STRIDE + 4]);
    const float4 a1 = *reinterpret_cast<const float4*>(&s[(tid + TPB) * IN_STRIDE]);
    const float4 b1 = *reinterpret_cast<const float4*>(&s[(tid + TPB) * IN_STRIDE + 4]);
    __syncthreads();   // all reads done before output stage overwrites buffer

    // 4) Compute and stage outputs (stride 9: gcd(9,32)=1, conflict-free STS).
    float fr0[9], fr1[9];
    compute_row(a0, b0, fr0);
    compute_row(a1, b1, fr1);
#pragma unroll
    for (int i = 0; i < 9; i++) s[tid * 9 + i] = fr0[i];
#pragma unroll
    for (int i = 0; i < 9; i++) s[(tid + TPB) * 9 + i] = fr1[i];
    __syncthreads();

    // 5) Coalesced block store: RPB*9 = 4608 floats = 1152 float4.
    const float4* s4 = reinterpret_cast<const float4*>(s);
    float4* out4 = reinterpret_cast<float4*>(out) + blk * 1152u;
#pragma unroll
    for (int k = 0; k < 4; k++)
        __stcs(&out4[k * TPB + tid], s4[k * TPB + tid]);
    if (tid < 128)
        __stcs(&out4[4 * TPB + tid], s4[4 * TPB + tid]);
}

// Generic fallback (any B).
__global__ __launch_bounds__(TPB)
void fmat_kernel_gen(const float* __restrict__ X, float* __restrict__ out, int B) {
    __shared__ float s[TPB * 9];
    const int tid = threadIdx.x;
    const long long row = (long long)blockIdx.x * TPB + tid;

    if (row < B) {
        const float4* Xv = reinterpret_cast<const float4*>(X);
        float4 a = Xv[row * 2 + 0];
        float4 b = Xv[row * 2 + 1];
        compute_row(a, b, &s[tid * 9]);
    }
    __syncthreads();

    const long long base = (long long)blockIdx.x * (TPB * 9);
    const long long total = (long long)B * 9;
#pragma unroll
    for (int k = 0; k < 9; k++) {
        long long idx = base + k * TPB + tid;
        if (idx < total) out[idx] = s[k * TPB + tid];
    }
}

extern "C" void kernel_launch(void* const* d_in, const int* in_sizes, int n_in,
                              void* d_out, int out_size) {
    const float* X = (const float*)d_in[0];
    float* out = (float*)d_out;
    const int B = in_sizes[0] / 8;
    if (B % RPB == 0) {
        fmat_kernel_fast<<<B / RPB, TPB>>>(X, out);
    } else {
        fmat_kernel_gen<<<(B + TPB - 1) / TPB, TPB>>>(X, out, B);
    }
}

// round 6
// speedup vs baseline: 1.1969x; 1.1969x over previous
#include <cuda_runtime.h>

// MatrixReconstructionLayer: X[B,8]=[f1,f2,rx,ry,rz,tx,ty,tz] -> F[B,9] (3x3 row-major).
// F = K2inv @ T @ R @ K1inv, closed-form. MUFU sin/cos + fast divide
// (rel_err ~3e-7 vs 1e-3 budget).
//
// R6 = R3 structure (best: 41.5us) with WARP-LOCAL output staging:
// each warp owns 64 rows, stages into its own smem slice, __syncwarp() only —
// no block barrier, warps drain independently. Warp's output region is 2304
// contiguous bytes -> stores stay perfectly coalesced STG.128.

#define EPSF 1e-8f
#define TPB 256
#define RPB (TPB * 2)          // 512 rows per block; 64 rows per warp

__device__ __forceinline__ void compute_row(const float4 a, const float4 b,
                                            float* __restrict__ sr) {
    const float f1 = a.x, f2 = a.y, rx = a.z, ry = a.w;
    const float rz = b.x, tx = b.y, ty = b.z, tz = b.w;

    const float sx = __sinf(rx), cx = __cosf(rx);
    const float sy = __sinf(ry), cy = __cosf(ry);
    const float sz = __sinf(rz), cz = __cosf(rz);

    const float k1 = -__fdividef(1.0f, f1 + EPSF);
    const float k2 = -__fdividef(1.0f, f2 + EPSF);

    // R = Rx @ (Ry @ Rz)
    const float sxsy = sx * sy;
    const float cxsy = cx * sy;

    const float r00 = cy * cz;
    const float r01 = -cy * sz;
    const float r02 = -sy;
    const float r10 = cx * sz - sxsy * cz;
    const float r11 = cx * cz + sxsy * sz;
    const float r12 = -sx * cy;
    const float r20 = sx * sz + cxsy * cz;
    const float r21 = sx * cz - cxsy * sz;
    const float r22 = cx * cy;

    // M = skew(t) @ R
    const float m00 = ty * r20 - tz * r10;
    const float m01 = ty * r21 - tz * r11;
    const float m02 = ty * r22 - tz * r12;
    const float m10 = tz * r00 - tx * r20;
    const float m11 = tz * r01 - tx * r21;
    const float m12 = tz * r02 - tx * r22;
    const float m20 = tx * r10 - ty * r00;
    const float m21 = tx * r11 - ty * r01;
    const float m22 = tx * r12 - ty * r02;

    // F = diag(k2,k2,1) @ M @ diag(k1,k1,1)
    const float k21 = k2 * k1;
    sr[0] = k21 * m00;
    sr[1] = k21 * m01;
    sr[2] = k2 * m02;
    sr[3] = k21 * m10;
    sr[4] = k21 * m11;
    sr[5] = k2 * m12;
    sr[6] = m20 * k1;
    sr[7] = m21 * k1;
    sr[8] = m22;
}

// Fast path: B % RPB == 0. Warp-local staging, no block barrier.
__global__ __launch_bounds__(TPB)
void fmat_kernel_fast(const float* __restrict__ X, float* __restrict__ out) {
    __shared__ __align__(16) float s[RPB * 9];   // 18KB; 576 floats per warp

    const int tid  = threadIdx.x;
    const int wid  = tid >> 5;          // warp 0..7
    const int lane = tid & 31;

    // Warp w owns rows [blk*512 + w*64, +64): lanes handle rows lane, lane+32.
    const unsigned warp_row0 = blockIdx.x * (unsigned)RPB + (unsigned)(wid * 64);
    const unsigned r0 = warp_row0 + lane;
    const unsigned r1 = r0 + 32;

    const float4* Xv = reinterpret_cast<const float4*>(X);
    // All 4 loads in flight before compute.
    const float4 a0 = __ldcs(&Xv[r0 * 2 + 0]);
    const float4 b0 = __ldcs(&Xv[r0 * 2 + 1]);
    const float4 a1 = __ldcs(&Xv[r1 * 2 + 0]);
    const float4 b1 = __ldcs(&Xv[r1 * 2 + 1]);

    float* sw = &s[wid * 576];          // this warp's slice
    compute_row(a0, b0, &sw[lane * 9]);           // stride 9: conflict-free
    compute_row(a1, b1, &sw[(lane + 32) * 9]);

    __syncwarp();

    // Warp output: 576 consecutive floats = 144 float4, contiguous in gmem.
    const float4* s4 = reinterpret_cast<const float4*>(sw);
    float4* out4 = reinterpret_cast<float4*>(out)
                 + (unsigned)blockIdx.x * 1152u + (unsigned)(wid * 144);
#pragma unroll
    for (int k = 0; k < 4; k++)
        __stcs(&out4[k * 32 + lane], s4[k * 32 + lane]);
    if (lane < 16)
        __stcs(&out4[128 + lane], s4[128 + lane]);
}

// Generic fallback (any B).
__global__ __launch_bounds__(TPB)
void fmat_kernel_gen(const float* __restrict__ X, float* __restrict__ out, int B) {
    __shared__ float s[TPB * 9];
    const int tid = threadIdx.x;
    const long long row = (long long)blockIdx.x * TPB + tid;

    if (row < B) {
        const float4* Xv = reinterpret_cast<const float4*>(X);
        float4 a = Xv[row * 2 + 0];
        float4 b = Xv[row * 2 + 1];
        compute_row(a, b, &s[tid * 9]);
    }
    __syncthreads();

    const long long base = (long long)blockIdx.x * (TPB * 9);
    const long long total = (long long)B * 9;
#pragma unroll
    for (int k = 0; k < 9; k++) {
        long long idx = base + k * TPB + tid;
        if (idx < total) out[idx] = s[k * TPB + tid];
    }
}

extern "C" void kernel_launch(void* const* d_in, const int* in_sizes, int n_in,
                              void* d_out, int out_size) {
    const float* X = (const float*)d_in[0];
    float* out = (float*)d_out;
    const int B = in_sizes[0] / 8;
    if (B % RPB == 0) {
        fmat_kernel_fast<<<B / RPB, TPB>>>(X, out);
    } else {
        fmat_kernel_gen<<<(B + TPB - 1) / TPB, TPB>>>(X, out, B);
    }
}